// round 5
// baseline (speedup 1.0000x reference)
#include <cuda_runtime.h>
#include <cstdint>

// ---------------------------------------------------------------------------
// ClassificationNCA: 20-step neural cellular automaton, fused per-step kernel.
// Round 5: 64-pixel tiles, 256 thr/CTA, 2 CTAs/SM, double-buffered weight
// staging with register prefetch (1 barrier/stage, latency hidden).
// All accumulation chains bit-identical to the round-3/4 passing kernels.
// ---------------------------------------------------------------------------

#define kNCH 29
#define kBatch 16
#define kPix 4096
#define kStateElems (kBatch * kNCH * kPix)
#define kSteps 20

// smem layout (floats)
#define kH1Off 8192               /* region A = 8192 floats: P[88][64] / H2[128][64] */
#define kWsOff (kH1Off + 16384)   /* H1 = 256*64 */
#define kWsBuf 2048               /* two 8KB staging buffers (contiguous) */
#define kSmemFloats (kWsOff + 2 * kWsBuf)
#define kSmemBytes (kSmemFloats * 4)   /* 114688 B -> 2 CTAs/SM */

__device__ float g_state[2][kStateElems];

// ---------------------------------------------------------------------------
// packed f32x2 helpers
// ---------------------------------------------------------------------------
__device__ __forceinline__ unsigned long long pack2(float x, float y)
{
    unsigned long long r;
    asm("mov.b64 %0, {%1, %2};" : "=l"(r) : "f"(x), "f"(y));
    return r;
}
__device__ __forceinline__ unsigned long long ffma2(unsigned long long a,
                                                    unsigned long long b,
                                                    unsigned long long c)
{
    unsigned long long d;
    asm("fma.rn.f32x2 %0, %1, %2, %3;" : "=l"(d) : "l"(a), "l"(b), "l"(c));
    return d;
}
__device__ __forceinline__ float2 unpack2(unsigned long long v)
{
    float2 f;
    asm("mov.b64 {%0, %1}, %2;" : "=f"(f.x), "=f"(f.y) : "l"(v));
    return f;
}

// ---------------------------------------------------------------------------
// threefry2x32, JAX key schedule (20 rounds)
// ---------------------------------------------------------------------------
#define TF_ROUND(r) { x0 += x1; x1 = (x1 << (r)) | (x1 >> (32 - (r))); x1 ^= x0; }
__host__ __device__ inline void threefry2x32(uint32_t k0, uint32_t k1,
                                             uint32_t x0, uint32_t x1,
                                             uint32_t &o0, uint32_t &o1)
{
    uint32_t k2 = k0 ^ k1 ^ 0x1BD11BDAu;
    x0 += k0; x1 += k1;
    TF_ROUND(13) TF_ROUND(15) TF_ROUND(26) TF_ROUND(6)
    x0 += k1; x1 += k2 + 1u;
    TF_ROUND(17) TF_ROUND(29) TF_ROUND(16) TF_ROUND(24)
    x0 += k2; x1 += k0 + 2u;
    TF_ROUND(13) TF_ROUND(15) TF_ROUND(26) TF_ROUND(6)
    x0 += k0; x1 += k1 + 3u;
    TF_ROUND(17) TF_ROUND(29) TF_ROUND(16) TF_ROUND(24)
    x0 += k1; x1 += k2 + 4u;
    TF_ROUND(13) TF_ROUND(15) TF_ROUND(26) TF_ROUND(6)
    x0 += k2; x1 += k0 + 5u;
    o0 = x0; o1 = x1;
}

// XLA ErfInv (f32), Giles polynomial — matches jax.lax.erf_inv
__device__ inline float erfinv_f(float x)
{
    float w = -log1pf(-x * x);
    float p;
    if (w < 5.0f) {
        w -= 2.5f;
        p = 2.81022636e-08f;
        p = fmaf(p, w, 3.43273939e-07f);
        p = fmaf(p, w, -3.5233877e-06f);
        p = fmaf(p, w, -4.39150654e-06f);
        p = fmaf(p, w, 0.00021858087f);
        p = fmaf(p, w, -0.00125372503f);
        p = fmaf(p, w, -0.00417768164f);
        p = fmaf(p, w, 0.246640727f);
        p = fmaf(p, w, 1.50140941f);
    } else {
        w = sqrtf(w) - 3.0f;
        p = -0.000200214257f;
        p = fmaf(p, w, 0.000100950558f);
        p = fmaf(p, w, 0.00134934322f);
        p = fmaf(p, w, -0.00367342844f);
        p = fmaf(p, w, 0.00573950773f);
        p = fmaf(p, w, -0.0076224613f);
        p = fmaf(p, w, 0.00943887047f);
        p = fmaf(p, w, 1.00167406f);
        p = fmaf(p, w, 2.83297682f);
    }
    return p * x;
}

// ---------------------------------------------------------------------------
// init: channels 0-2 = image (both buffers), 3-18 = threefry normal, 19-28 = 0
// ---------------------------------------------------------------------------
__global__ void __launch_bounds__(256) nca_init_kernel(const float* __restrict__ x,
                                                       uint32_t hk0, uint32_t hk1)
{
    int e = blockIdx.x * 256 + threadIdx.x;
    if (e >= kStateElems) return;
    int b = e / (kNCH * kPix);
    int r = e - b * (kNCH * kPix);
    int c = r / kPix;
    int pix = r - c * kPix;

    if (c < 3) {
        float v = x[(b * 3 + c) * kPix + pix];
        g_state[0][e] = v;
        g_state[1][e] = v;
    } else if (c < 19) {
        const uint32_t HALF = 524288u;  // (16*16*4096)/2
        uint32_t i = (uint32_t)((b * 16 + (c - 3)) * kPix + pix);
        uint32_t lo = (i < HALF) ? i : (i - HALF);
        uint32_t o0, o1;
        threefry2x32(hk0, hk1, lo, lo + HALF, o0, o1);
        uint32_t bits = (i < HALF) ? o0 : o1;
        float f = __uint_as_float((bits >> 9) | 0x3f800000u) - 1.0f;
        const float LOV = -0.99999994f;               // nextafter(-1, 0)
        float u = fmaxf(LOV, f * 2.0f + LOV);         // (hi - lo) rounds to 2.0f
        float z = 1.41421356f * erfinv_f(u);
        g_state[0][e] = 0.5f + 0.225f * z;
    } else {
        g_state[0][e] = 0.0f;
    }
}

// ---------------------------------------------------------------------------
// weight stage stream:
//  g in [0,16):  layer1, chunk c=g>>2 (8 outs/warp), kstage s=g&3, ks=s*22
//  g in [16,32): layer2, chunk c=(g-16)>>3, kstage s=(g-16)&7, ks=s*32
//  g == 32:      w3[0:2048)     g == 33: w3[2048:3712)
// ---------------------------------------------------------------------------
__device__ __forceinline__ void stage_prefetch(int g, int tid,
    const float* __restrict__ w1, const float* __restrict__ w2,
    const float* __restrict__ w3, float pf[8])
{
    if (g < 16) {
        int c = g >> 2, s = g & 3, ks = s * 22;
#pragma unroll
        for (int t = 0; t < 6; ++t) {
            int i = tid + t * 256;
            if (i < 1408) {
                int kk = i >> 6, ol = i & 63;
                int row = ((ol >> 3) << 5) + c * 8 + (ol & 7);
                pf[t] = __ldg(&w1[row * 88 + ks + kk]);
            }
        }
    } else if (g < 32) {
        int c = (g - 16) >> 3, s = (g - 16) & 7, ks = s * 32;
#pragma unroll
        for (int t = 0; t < 8; ++t) {
            int i = tid + t * 256;
            int kk = i >> 6, ol = i & 63;
            int row = ((ol >> 3) << 4) + c * 8 + (ol & 7);
            pf[t] = __ldg(&w2[row * 256 + ks + kk]);
        }
    } else if (g == 32) {
#pragma unroll
        for (int t = 0; t < 8; ++t) pf[t] = __ldg(&w3[tid + t * 256]);
    } else if (g == 33) {
#pragma unroll
        for (int t = 0; t < 7; ++t) {
            int i = tid + t * 256;
            if (i < 1664) pf[t] = __ldg(&w3[2048 + i]);
        }
    }
}

__device__ __forceinline__ void stage_store(int g, int tid, float* Ws, float pf[8])
{
    if (g < 16) {
        float* buf = Ws + (g & 1) * kWsBuf;
#pragma unroll
        for (int t = 0; t < 6; ++t) {
            int i = tid + t * 256;
            if (i < 1408) buf[i] = pf[t];
        }
    } else if (g < 32) {
        float* buf = Ws + (g & 1) * kWsBuf;
#pragma unroll
        for (int t = 0; t < 8; ++t) buf[tid + t * 256] = pf[t];
    } else if (g == 32) {
        // (32&1)==0 -> Ws[0:2048) == w3[0:2048)
#pragma unroll
        for (int t = 0; t < 8; ++t) Ws[tid + t * 256] = pf[t];
    } else if (g == 33) {
        // (33&1)==1 -> Ws[2048:3712) == w3[2048:3712)
#pragma unroll
        for (int t = 0; t < 7; ++t) {
            int i = tid + t * 256;
            if (i < 1664) Ws[2048 + i] = pf[t];
        }
    }
}

// ---------------------------------------------------------------------------
// fused NCA step: perception -> 88->256->128->29 MLP -> fire-masked update
// block = 64 pixels (16x4 tile), 256 threads, grid (4, 16, 16), 2 CTAs/SM
// ---------------------------------------------------------------------------
__global__ void __launch_bounds__(256, 2) nca_step_kernel(
    const float* __restrict__ w1, const float* __restrict__ b1,
    const float* __restrict__ w2, const float* __restrict__ w3,
    float tval, uint32_t fk0, uint32_t fk1, int srcbuf)
{
    extern __shared__ float smem[];
    float* P   = smem;           // [88][64]
    float* H1s = smem + kH1Off;  // [256][64]
    float* H2s = smem;           // [128][64] (reuses P region)
    float* Ws  = smem + kWsOff;  // 2 x 2048-float staging buffers (contiguous)

    const float* __restrict__ src = g_state[srcbuf];
    float* __restrict__ dst = g_state[srcbuf ^ 1];

    const int tid = threadIdx.x;
    const int b  = blockIdx.z;
    const int x0 = blockIdx.x * 16;
    const int y0 = blockIdx.y * 4;
    const int pix  = tid & 63;
    const int grp4 = tid >> 6;          // 0..3
    const int tx = pix & 15;
    const int ty = pix >> 4;            // 0..3
    const int gx = x0 + tx;
    const int gy = y0 + ty;

    float pf[8];
    // prefetch stage 0 weights; latency overlaps perception's global loads
    stage_prefetch(0, tid, w1, w2, w3, pf);

    // ---- phase 1: perception (s, sobel_x, sobel_y, t) -> P ----
    {
        const float* sb = src + b * (kNCH * kPix);
        const int cbeg = grp4 * 8;
        const int cend = (cbeg + 8 < 29) ? cbeg + 8 : 29;
        const bool ym = gy > 0, yp = gy < 63, xm = gx > 0, xp = gx < 63;
        for (int c = cbeg; c < cend; ++c) {
            const float* sc = sb + c * kPix;
            float v11 = __ldg(&sc[gy * 64 + gx]);
            float v01 = ym ? __ldg(&sc[(gy - 1) * 64 + gx]) : 0.f;
            float v21 = yp ? __ldg(&sc[(gy + 1) * 64 + gx]) : 0.f;
            float v10 = xm ? __ldg(&sc[gy * 64 + gx - 1]) : 0.f;
            float v12 = xp ? __ldg(&sc[gy * 64 + gx + 1]) : 0.f;
            float v00 = (ym && xm) ? __ldg(&sc[(gy - 1) * 64 + gx - 1]) : 0.f;
            float v02 = (ym && xp) ? __ldg(&sc[(gy - 1) * 64 + gx + 1]) : 0.f;
            float v20 = (yp && xm) ? __ldg(&sc[(gy + 1) * 64 + gx - 1]) : 0.f;
            float v22 = (yp && xp) ? __ldg(&sc[(gy + 1) * 64 + gx + 1]) : 0.f;
            float sx = ((v02 - v00) + 2.0f * (v12 - v10) + (v22 - v20)) * 0.125f;
            float sy = ((v20 - v00) + 2.0f * (v21 - v01) + (v22 - v02)) * 0.125f;
            P[c * 64 + pix] = v11;
            P[(29 + c) * 64 + pix] = sx;
            P[(58 + c) * 64 + pix] = sy;
        }
        if (grp4 == 0) P[87 * 64 + pix] = tval;
    }

    stage_store(0, tid, Ws, pf);
    stage_prefetch(1, tid, w1, w2, w3, pf);
    __syncthreads();   // P ready, Ws buf0 ready

    const int og = tid >> 5;          // warp 0..7 (uniform -> broadcast LDS)
    const int pb = (tid & 31) * 2;    // 2 pixels per thread

    // ---- layer 1: h1 = leaky(W1 @ p + b1), 256 outs, k = 88 (4x22) ----
    for (int c = 0; c < 4; ++c) {
        const int obase = og * 32 + c * 8;
        unsigned long long acc[4][2];
#pragma unroll
        for (int p = 0; p < 4; ++p) {
            unsigned long long bp = pack2(__ldg(&b1[obase + 2 * p]),
                                          __ldg(&b1[obase + 2 * p + 1]));
            acc[p][0] = bp; acc[p][1] = bp;
        }
        for (int s = 0; s < 4; ++s) {
            const int g = c * 4 + s;
            const float* buf = Ws + (g & 1) * kWsBuf;
            const int ks = s * 22;
#pragma unroll 2
            for (int kk = 0; kk < 22; ++kk) {
                float2 pv = *reinterpret_cast<const float2*>(&P[(ks + kk) * 64 + pb]);
                ulonglong2 wA = *reinterpret_cast<const ulonglong2*>(&buf[kk * 64 + og * 8]);
                ulonglong2 wB = *reinterpret_cast<const ulonglong2*>(&buf[kk * 64 + og * 8 + 4]);
                unsigned long long p0 = pack2(pv.x, pv.x);
                unsigned long long p1 = pack2(pv.y, pv.y);
                acc[0][0] = ffma2(wA.x, p0, acc[0][0]);
                acc[0][1] = ffma2(wA.x, p1, acc[0][1]);
                acc[1][0] = ffma2(wA.y, p0, acc[1][0]);
                acc[1][1] = ffma2(wA.y, p1, acc[1][1]);
                acc[2][0] = ffma2(wB.x, p0, acc[2][0]);
                acc[2][1] = ffma2(wB.x, p1, acc[2][1]);
                acc[3][0] = ffma2(wB.y, p0, acc[3][0]);
                acc[3][1] = ffma2(wB.y, p1, acc[3][1]);
            }
            stage_store(g + 1, tid, Ws, pf);
            stage_prefetch(g + 2, tid, w1, w2, w3, pf);
            __syncthreads();
        }
#pragma unroll
        for (int p = 0; p < 4; ++p) {
            float2 f0 = unpack2(acc[p][0]);
            float2 f1 = unpack2(acc[p][1]);
            float a0 = f0.x >= 0.f ? f0.x : 0.01f * f0.x;
            float a1 = f1.x >= 0.f ? f1.x : 0.01f * f1.x;
            float b0v = f0.y >= 0.f ? f0.y : 0.01f * f0.y;
            float b1v = f1.y >= 0.f ? f1.y : 0.01f * f1.y;
            *reinterpret_cast<float2*>(&H1s[(obase + 2 * p) * 64 + pb]) = make_float2(a0, a1);
            *reinterpret_cast<float2*>(&H1s[(obase + 2 * p + 1) * 64 + pb]) = make_float2(b0v, b1v);
        }
    }
    __syncthreads();   // all H1 written before layer2 reads it

    // ---- layer 2: h2 = leaky(W2 @ h1), 128 outs, k = 256 (8x32) ----
    for (int c = 0; c < 2; ++c) {
        const int obase = og * 16 + c * 8;
        unsigned long long acc[4][2];
#pragma unroll
        for (int p = 0; p < 4; ++p) { acc[p][0] = 0ull; acc[p][1] = 0ull; }
        for (int s = 0; s < 8; ++s) {
            const int g = 16 + c * 8 + s;
            const float* buf = Ws + (g & 1) * kWsBuf;
            const int ks = s * 32;
#pragma unroll 2
            for (int kk = 0; kk < 32; ++kk) {
                float2 hv = *reinterpret_cast<const float2*>(&H1s[(ks + kk) * 64 + pb]);
                ulonglong2 wA = *reinterpret_cast<const ulonglong2*>(&buf[kk * 64 + og * 8]);
                ulonglong2 wB = *reinterpret_cast<const ulonglong2*>(&buf[kk * 64 + og * 8 + 4]);
                unsigned long long p0 = pack2(hv.x, hv.x);
                unsigned long long p1 = pack2(hv.y, hv.y);
                acc[0][0] = ffma2(wA.x, p0, acc[0][0]);
                acc[0][1] = ffma2(wA.x, p1, acc[0][1]);
                acc[1][0] = ffma2(wA.y, p0, acc[1][0]);
                acc[1][1] = ffma2(wA.y, p1, acc[1][1]);
                acc[2][0] = ffma2(wB.x, p0, acc[2][0]);
                acc[2][1] = ffma2(wB.x, p1, acc[2][1]);
                acc[3][0] = ffma2(wB.y, p0, acc[3][0]);
                acc[3][1] = ffma2(wB.y, p1, acc[3][1]);
            }
            stage_store(g + 1, tid, Ws, pf);
            stage_prefetch(g + 2, tid, w1, w2, w3, pf);
            __syncthreads();
        }
#pragma unroll
        for (int p = 0; p < 4; ++p) {
            float2 f0 = unpack2(acc[p][0]);
            float2 f1 = unpack2(acc[p][1]);
            float a0 = f0.x >= 0.f ? f0.x : 0.01f * f0.x;
            float a1 = f1.x >= 0.f ? f1.x : 0.01f * f1.x;
            float b0v = f0.y >= 0.f ? f0.y : 0.01f * f0.y;
            float b1v = f1.y >= 0.f ? f1.y : 0.01f * f1.y;
            *reinterpret_cast<float2*>(&H2s[(obase + 2 * p) * 64 + pb]) = make_float2(a0, a1);
            *reinterpret_cast<float2*>(&H2s[(obase + 2 * p + 1) * 64 + pb]) = make_float2(b0v, b1v);
        }
    }

    // finish staging w3 (pf holds stage 33 from the last prefetch)
    stage_store(33, tid, Ws, pf);
    __syncthreads();   // H2 + full w3 visible

    // ---- layer 3 (channels 3..28 only; 0..2 are masked) + fire update ----
    {
        // grp4 0..3 handle {7,7,6,6} channels starting at {3,10,17,23}
        const int obase = (grp4 < 2) ? (3 + grp4 * 7) : (17 + (grp4 - 2) * 6);
        const int cnt   = (grp4 < 2) ? 7 : 6;
        float dxv[7];
#pragma unroll
        for (int u = 0; u < 7; ++u) dxv[u] = 0.f;
#pragma unroll 2
        for (int k = 0; k < 128; ++k) {
            float h = H2s[k * 64 + pix];
#pragma unroll
            for (int u = 0; u < 7; ++u)
                dxv[u] = fmaf(Ws[(obase + u) * 128 + k], h, dxv[u]);
        }
        // fire mask: uniform(fold_in(key, step), (B,H,W,1)) < 0.5  <=>  top bit 0
        uint32_t n = (uint32_t)(b * 4096 + gy * 64 + gx);
        const uint32_t HALF = 32768u;
        uint32_t lo = (n < HALF) ? n : (n - HALF);
        uint32_t o0, o1;
        threefry2x32(fk0, fk1, lo, lo + HALF, o0, o1);
        uint32_t bits = (n < HALF) ? o0 : o1;
        bool fire = (bits & 0x80000000u) == 0u;

        int base = (b * kNCH) * kPix + gy * 64 + gx;
#pragma unroll
        for (int u = 0; u < 7; ++u) {
            if (u < cnt) {
                int idx = base + (obase + u) * kPix;
                float s = __ldg(&src[idx]);
                dst[idx] = fire ? (s + dxv[u]) : s;
            }
        }
    }
}

// ---------------------------------------------------------------------------
// reduce: mean over HW of channels 19..28, then softmax -> out (16, 10)
// ---------------------------------------------------------------------------
__global__ void __launch_bounds__(256) nca_reduce_kernel(float* __restrict__ out)
{
    int b = blockIdx.x;
    int tid = threadIdx.x;
    const float* st = g_state[0] + (b * kNCH + 19) * kPix;
    float acc[10];
#pragma unroll
    for (int c = 0; c < 10; ++c) acc[c] = 0.f;
    for (int i = tid; i < kPix; i += 256) {
#pragma unroll
        for (int c = 0; c < 10; ++c) acc[c] += st[c * kPix + i];
    }
#pragma unroll
    for (int c = 0; c < 10; ++c) {
#pragma unroll
        for (int off = 16; off > 0; off >>= 1)
            acc[c] += __shfl_xor_sync(0xffffffffu, acc[c], off);
    }
    __shared__ float sred[10][8];
    int wid = tid >> 5, lane = tid & 31;
    if (lane == 0) {
#pragma unroll
        for (int c = 0; c < 10; ++c) sred[c][wid] = acc[c];
    }
    __syncthreads();
    if (tid == 0) {
        float m[10];
        float mx = -1e30f;
#pragma unroll
        for (int c = 0; c < 10; ++c) {
            float s = 0.f;
#pragma unroll
            for (int w = 0; w < 8; ++w) s += sred[c][w];
            m[c] = s * (1.0f / 4096.0f);
            mx = fmaxf(mx, m[c]);
        }
        float den = 0.f;
        float e[10];
#pragma unroll
        for (int c = 0; c < 10; ++c) { e[c] = expf(m[c] - mx); den += e[c]; }
#pragma unroll
        for (int c = 0; c < 10; ++c) out[b * 10 + c] = e[c] / den;
    }
}

// ---------------------------------------------------------------------------
extern "C" void kernel_launch(void* const* d_in, const int* in_sizes, int n_in,
                              void* d_out, int out_size)
{
    (void)in_sizes; (void)n_in; (void)out_size;
    const float* x  = (const float*)d_in[0];
    const float* w1 = (const float*)d_in[1];
    const float* b1 = (const float*)d_in[2];
    const float* w2 = (const float*)d_in[3];
    const float* w3 = (const float*)d_in[4];
    float* out = (float*)d_out;

    cudaFuncSetAttribute(nca_step_kernel,
                         cudaFuncAttributeMaxDynamicSharedMemorySize, kSmemBytes);

    // hid-init key: fold_in(key(42), 10000)
    uint32_t hk0, hk1;
    threefry2x32(0u, 42u, 0u, 10000u, hk0, hk1);
    nca_init_kernel<<<(kStateElems + 255) / 256, 256>>>(x, hk0, hk1);

    for (int s = 0; s < kSteps; ++s) {
        uint32_t fk0, fk1;
        threefry2x32(0u, 42u, 0u, (uint32_t)s, fk0, fk1);
        nca_step_kernel<<<dim3(4, 16, 16), 256, kSmemBytes>>>(
            w1, b1, w2, w3, (float)s / 100.0f, fk0, fk1, s & 1);
    }
    nca_reduce_kernel<<<16, 256>>>(out);
}

// round 7
// speedup vs baseline: 1.0957x; 1.0957x over previous
#include <cuda_runtime.h>
#include <cstdint>

// ---------------------------------------------------------------------------
// ClassificationNCA: 20-step neural cellular automaton, fused per-step kernel.
// Round 6: 128-pixel tiles / 512 threads (round-4 shape), pixel-paired FFMA2
// with pre-duplicated weights in smem (zero ALU packs), double-buffered
// weight staging with register prefetch (no exposed LDG latency at barriers).
// All accumulation chains bit-identical to the round-3/4 passing kernels.
// ---------------------------------------------------------------------------

#define kNCH 29
#define kBatch 16
#define kPix 4096
#define kStateElems (kBatch * kNCH * kPix)
#define kSteps 20

// smem layout (floats)
#define kH1Off 16384              /* region A: P[88][128] / H2[128][128] */
#define kWsOff (kH1Off + 32768)   /* H1 = 256*128 */
#define kWsBuf 4096               /* two 16KB staging buffers */
#define kSmemFloats (kWsOff + 2 * kWsBuf)
#define kSmemBytes (kSmemFloats * 4)   /* 229376 B -> 1 CTA/SM */

__device__ float g_state[2][kStateElems];

// ---------------------------------------------------------------------------
// packed f32x2 helpers
// ---------------------------------------------------------------------------
__device__ __forceinline__ unsigned long long pack2(float x, float y)
{
    unsigned long long r;
    asm("mov.b64 %0, {%1, %2};" : "=l"(r) : "f"(x), "f"(y));
    return r;
}
__device__ __forceinline__ unsigned long long ffma2(unsigned long long a,
                                                    unsigned long long b,
                                                    unsigned long long c)
{
    unsigned long long d;
    asm("fma.rn.f32x2 %0, %1, %2, %3;" : "=l"(d) : "l"(a), "l"(b), "l"(c));
    return d;
}
__device__ __forceinline__ float2 unpack2(unsigned long long v)
{
    float2 f;
    asm("mov.b64 {%0, %1}, %2;" : "=f"(f.x), "=f"(f.y) : "l"(v));
    return f;
}

// ---------------------------------------------------------------------------
// threefry2x32, JAX key schedule (20 rounds)
// ---------------------------------------------------------------------------
#define TF_ROUND(r) { x0 += x1; x1 = (x1 << (r)) | (x1 >> (32 - (r))); x1 ^= x0; }
__host__ __device__ inline void threefry2x32(uint32_t k0, uint32_t k1,
                                             uint32_t x0, uint32_t x1,
                                             uint32_t &o0, uint32_t &o1)
{
    uint32_t k2 = k0 ^ k1 ^ 0x1BD11BDAu;
    x0 += k0; x1 += k1;
    TF_ROUND(13) TF_ROUND(15) TF_ROUND(26) TF_ROUND(6)
    x0 += k1; x1 += k2 + 1u;
    TF_ROUND(17) TF_ROUND(29) TF_ROUND(16) TF_ROUND(24)
    x0 += k2; x1 += k0 + 2u;
    TF_ROUND(13) TF_ROUND(15) TF_ROUND(26) TF_ROUND(6)
    x0 += k0; x1 += k1 + 3u;
    TF_ROUND(17) TF_ROUND(29) TF_ROUND(16) TF_ROUND(24)
    x0 += k1; x1 += k2 + 4u;
    TF_ROUND(13) TF_ROUND(15) TF_ROUND(26) TF_ROUND(6)
    x0 += k2; x1 += k0 + 5u;
    o0 = x0; o1 = x1;
}

// XLA ErfInv (f32), Giles polynomial — matches jax.lax.erf_inv
__device__ inline float erfinv_f(float x)
{
    float w = -log1pf(-x * x);
    float p;
    if (w < 5.0f) {
        w -= 2.5f;
        p = 2.81022636e-08f;
        p = fmaf(p, w, 3.43273939e-07f);
        p = fmaf(p, w, -3.5233877e-06f);
        p = fmaf(p, w, -4.39150654e-06f);
        p = fmaf(p, w, 0.00021858087f);
        p = fmaf(p, w, -0.00125372503f);
        p = fmaf(p, w, -0.00417768164f);
        p = fmaf(p, w, 0.246640727f);
        p = fmaf(p, w, 1.50140941f);
    } else {
        w = sqrtf(w) - 3.0f;
        p = -0.000200214257f;
        p = fmaf(p, w, 0.000100950558f);
        p = fmaf(p, w, 0.00134934322f);
        p = fmaf(p, w, -0.00367342844f);
        p = fmaf(p, w, 0.00573950773f);
        p = fmaf(p, w, -0.0076224613f);
        p = fmaf(p, w, 0.00943887047f);
        p = fmaf(p, w, 1.00167406f);
        p = fmaf(p, w, 2.83297682f);
    }
    return p * x;
}

// ---------------------------------------------------------------------------
// init: channels 0-2 = image (both buffers), 3-18 = threefry normal, 19-28 = 0
// ---------------------------------------------------------------------------
__global__ void __launch_bounds__(256) nca_init_kernel(const float* __restrict__ x,
                                                       uint32_t hk0, uint32_t hk1)
{
    int e = blockIdx.x * 256 + threadIdx.x;
    if (e >= kStateElems) return;
    int b = e / (kNCH * kPix);
    int r = e - b * (kNCH * kPix);
    int c = r / kPix;
    int pix = r - c * kPix;

    if (c < 3) {
        float v = x[(b * 3 + c) * kPix + pix];
        g_state[0][e] = v;
        g_state[1][e] = v;
    } else if (c < 19) {
        const uint32_t HALF = 524288u;  // (16*16*4096)/2
        uint32_t i = (uint32_t)((b * 16 + (c - 3)) * kPix + pix);
        uint32_t lo = (i < HALF) ? i : (i - HALF);
        uint32_t o0, o1;
        threefry2x32(hk0, hk1, lo, lo + HALF, o0, o1);
        uint32_t bits = (i < HALF) ? o0 : o1;
        float f = __uint_as_float((bits >> 9) | 0x3f800000u) - 1.0f;
        const float LOV = -0.99999994f;               // nextafter(-1, 0)
        float u = fmaxf(LOV, f * 2.0f + LOV);         // (hi - lo) rounds to 2.0f
        float z = 1.41421356f * erfinv_f(u);
        g_state[0][e] = 0.5f + 0.225f * z;
    } else {
        g_state[0][e] = 0.0f;
    }
}

// ---------------------------------------------------------------------------
// weight stage stream (stages of duplicated (w,w) pairs):
//  g in [0,16):  layer1, chunk c=g>>3, kstage s=g&7, ks=s*11  (11 k, 128 outs)
//  g in [16,32): layer2, kstage s=g-16, ks=s*16               (16 k, 128 outs)
//  g == 32:      w3 (3712 floats, NOT duplicated)
//  buffer for stage g: Ws + (g&1)*kWsBuf
// ---------------------------------------------------------------------------
__device__ __forceinline__ void stage_prefetch(int g, int tid,
    const float* __restrict__ w1, const float* __restrict__ w2,
    const float* __restrict__ w3, float pf[8])
{
    if (g < 16) {
        int c = g >> 3, s = g & 7, ks = s * 11;
#pragma unroll
        for (int t = 0; t < 3; ++t) {
            int i = tid + t * 512;
            if (i < 11 * 128) {
                int kk = i >> 7, ol = i & 127;
                int row = ((ol >> 3) << 4) + c * 8 + (ol & 7);
                pf[t] = __ldg(&w1[row * 88 + ks + kk]);
            }
        }
    } else if (g < 32) {
        int s = g - 16, ks = s * 16;
#pragma unroll
        for (int t = 0; t < 4; ++t) {
            int i = tid + t * 512;
            int kk = i >> 7, ol = i & 127;
            pf[t] = __ldg(&w2[ol * 256 + ks + kk]);
        }
    } else if (g == 32) {
#pragma unroll
        for (int t = 0; t < 8; ++t) {
            int i = tid + t * 512;
            if (i < 3712) pf[t] = __ldg(&w3[i]);
        }
    }
}

__device__ __forceinline__ void stage_store(int g, int tid, float* Ws, float pf[8])
{
    if (g < 16) {
        float* buf = Ws + (g & 1) * kWsBuf;
#pragma unroll
        for (int t = 0; t < 3; ++t) {
            int i = tid + t * 512;
            if (i < 11 * 128) {
                int kk = i >> 7, ol = i & 127;
                *reinterpret_cast<float2*>(&buf[kk * 256 + ol * 2]) =
                    make_float2(pf[t], pf[t]);
            }
        }
    } else if (g < 32) {
        float* buf = Ws + (g & 1) * kWsBuf;
#pragma unroll
        for (int t = 0; t < 4; ++t) {
            int i = tid + t * 512;
            int kk = i >> 7, ol = i & 127;
            *reinterpret_cast<float2*>(&buf[kk * 256 + ol * 2]) =
                make_float2(pf[t], pf[t]);
        }
    } else if (g == 32) {
        // (32&1)==0 -> Ws[0:3712) holds w3 verbatim
#pragma unroll
        for (int t = 0; t < 8; ++t) {
            int i = tid + t * 512;
            if (i < 3712) Ws[i] = pf[t];
        }
    }
}

// 16 pixel-paired FFMA2s for one k: 8 outs x 2 pixel-pairs
#define MLP_K_STEP(SRC, kidx, buf, kk)                                          \
    {                                                                            \
        ulonglong2 pv = *reinterpret_cast<const ulonglong2*>(&SRC[(kidx) * 128 + pb]); \
        const ulonglong2* wr = reinterpret_cast<const ulonglong2*>(&buf[(kk) * 256 + og * 16]); \
        ulonglong2 wa = wr[0], wb = wr[1], wc = wr[2], wd = wr[3];               \
        acc[0][0] = ffma2(wa.x, pv.x, acc[0][0]); acc[0][1] = ffma2(wa.x, pv.y, acc[0][1]); \
        acc[1][0] = ffma2(wa.y, pv.x, acc[1][0]); acc[1][1] = ffma2(wa.y, pv.y, acc[1][1]); \
        acc[2][0] = ffma2(wb.x, pv.x, acc[2][0]); acc[2][1] = ffma2(wb.x, pv.y, acc[2][1]); \
        acc[3][0] = ffma2(wb.y, pv.x, acc[3][0]); acc[3][1] = ffma2(wb.y, pv.y, acc[3][1]); \
        acc[4][0] = ffma2(wc.x, pv.x, acc[4][0]); acc[4][1] = ffma2(wc.x, pv.y, acc[4][1]); \
        acc[5][0] = ffma2(wc.y, pv.x, acc[5][0]); acc[5][1] = ffma2(wc.y, pv.y, acc[5][1]); \
        acc[6][0] = ffma2(wd.x, pv.x, acc[6][0]); acc[6][1] = ffma2(wd.x, pv.y, acc[6][1]); \
        acc[7][0] = ffma2(wd.y, pv.x, acc[7][0]); acc[7][1] = ffma2(wd.y, pv.y, acc[7][1]); \
    }

// ---------------------------------------------------------------------------
// fused NCA step: perception -> 88->256->128->29 MLP -> fire-masked update
// block = 128 pixels (16x8 tile), 512 threads, grid (4, 8, 16), 1 CTA/SM
// ---------------------------------------------------------------------------
__global__ void __launch_bounds__(512, 1) nca_step_kernel(
    const float* __restrict__ w1, const float* __restrict__ b1,
    const float* __restrict__ w2, const float* __restrict__ w3,
    float tval, uint32_t fk0, uint32_t fk1, int srcbuf)
{
    extern __shared__ float smem[];
    float* P   = smem;           // [88][128]
    float* H1s = smem + kH1Off;  // [256][128]
    float* H2s = smem;           // [128][128] (reuses P region)
    float* Ws  = smem + kWsOff;  // 2 x 4096-float staging buffers

    const float* __restrict__ src = g_state[srcbuf];
    float* __restrict__ dst = g_state[srcbuf ^ 1];

    const int tid = threadIdx.x;
    const int b  = blockIdx.z;
    const int x0 = blockIdx.x * 16;
    const int y0 = blockIdx.y * 8;
    const int pix  = tid & 127;
    const int grp4 = tid >> 7;          // 0..3
    const int tx = pix & 15;
    const int ty = pix >> 4;
    const int gx = x0 + tx;
    const int gy = y0 + ty;

    float pf[8];
    // prefetch stage 0; its latency overlaps perception's global loads
    stage_prefetch(0, tid, w1, w2, w3, pf);

    // ---- phase 1: perception (s, sobel_x, sobel_y, t) -> P ----
    {
        const float* sb = src + b * (kNCH * kPix);
        const int cbeg = grp4 * 8;
        const int cend = (cbeg + 8 < 29) ? cbeg + 8 : 29;
        const bool ym = gy > 0, yp = gy < 63, xm = gx > 0, xp = gx < 63;
        for (int c = cbeg; c < cend; ++c) {
            const float* sc = sb + c * kPix;
            float v11 = __ldg(&sc[gy * 64 + gx]);
            float v01 = ym ? __ldg(&sc[(gy - 1) * 64 + gx]) : 0.f;
            float v21 = yp ? __ldg(&sc[(gy + 1) * 64 + gx]) : 0.f;
            float v10 = xm ? __ldg(&sc[gy * 64 + gx - 1]) : 0.f;
            float v12 = xp ? __ldg(&sc[gy * 64 + gx + 1]) : 0.f;
            float v00 = (ym && xm) ? __ldg(&sc[(gy - 1) * 64 + gx - 1]) : 0.f;
            float v02 = (ym && xp) ? __ldg(&sc[(gy - 1) * 64 + gx + 1]) : 0.f;
            float v20 = (yp && xm) ? __ldg(&sc[(gy + 1) * 64 + gx - 1]) : 0.f;
            float v22 = (yp && xp) ? __ldg(&sc[(gy + 1) * 64 + gx + 1]) : 0.f;
            float sx = ((v02 - v00) + 2.0f * (v12 - v10) + (v22 - v20)) * 0.125f;
            float sy = ((v20 - v00) + 2.0f * (v21 - v01) + (v22 - v02)) * 0.125f;
            P[c * 128 + pix] = v11;
            P[(29 + c) * 128 + pix] = sx;
            P[(58 + c) * 128 + pix] = sy;
        }
        if (grp4 == 0) P[87 * 128 + pix] = tval;
    }

    stage_store(0, tid, Ws, pf);
    stage_prefetch(1, tid, w1, w2, w3, pf);
    __syncthreads();   // P ready, Ws buf0 ready
    // invariant: entering stage g, pf holds stage g+1's weights

    const int og = tid >> 5;          // warp id 0..15 (uniform -> broadcast LDS)
    const int pb = (tid & 31) << 2;   // pixel base, 4 pixels / thread

    // ---- layer 1: h1 = leaky(W1 @ p + b1), 256 outs, k = 88 (8 x 11) ----
    for (int c = 0; c < 2; ++c) {
        const int obase = og * 16 + c * 8;
        unsigned long long acc[8][2];
#pragma unroll
        for (int u = 0; u < 8; ++u) {
            float bb = __ldg(&b1[obase + u]);
            unsigned long long bp = pack2(bb, bb);
            acc[u][0] = bp; acc[u][1] = bp;
        }
        for (int s = 0; s < 8; ++s) {
            const int g = c * 8 + s;
            const float* buf = Ws + (g & 1) * kWsBuf;
            const int ks = s * 11;
#pragma unroll
            for (int kk = 0; kk < 11; ++kk) {
                MLP_K_STEP(P, ks + kk, buf, kk)
            }
            stage_store(g + 1, tid, Ws, pf);
            stage_prefetch(g + 2, tid, w1, w2, w3, pf);
            __syncthreads();
        }
#pragma unroll
        for (int u = 0; u < 8; ++u) {
            float2 f0 = unpack2(acc[u][0]);   // pixels pb+0, pb+1
            float2 f1 = unpack2(acc[u][1]);   // pixels pb+2, pb+3
            float4 hv;
            hv.x = f0.x >= 0.f ? f0.x : 0.01f * f0.x;
            hv.y = f0.y >= 0.f ? f0.y : 0.01f * f0.y;
            hv.z = f1.x >= 0.f ? f1.x : 0.01f * f1.x;
            hv.w = f1.y >= 0.f ? f1.y : 0.01f * f1.y;
            *reinterpret_cast<float4*>(&H1s[(obase + u) * 128 + pb]) = hv;
        }
    }
    __syncthreads();   // all H1 visible before layer2 reads it

    // ---- layer 2: h2 = leaky(W2 @ h1), 128 outs, k = 256 (16 x 16) ----
    {
        const int obase = og * 8;
        unsigned long long acc[8][2];
#pragma unroll
        for (int u = 0; u < 8; ++u) { acc[u][0] = 0ull; acc[u][1] = 0ull; }
        for (int s = 0; s < 16; ++s) {
            const int g = 16 + s;
            const float* buf = Ws + (g & 1) * kWsBuf;
            const int ks = s * 16;
#pragma unroll
            for (int kk = 0; kk < 16; ++kk) {
                MLP_K_STEP(H1s, ks + kk, buf, kk)
            }
            stage_store(g + 1, tid, Ws, pf);     // g=31 stores w3 into Ws[0:3712)
            stage_prefetch(g + 2, tid, w1, w2, w3, pf);
            __syncthreads();
        }
#pragma unroll
        for (int u = 0; u < 8; ++u) {
            float2 f0 = unpack2(acc[u][0]);
            float2 f1 = unpack2(acc[u][1]);
            float4 hv;
            hv.x = f0.x >= 0.f ? f0.x : 0.01f * f0.x;
            hv.y = f0.y >= 0.f ? f0.y : 0.01f * f0.y;
            hv.z = f1.x >= 0.f ? f1.x : 0.01f * f1.x;
            hv.w = f1.y >= 0.f ? f1.y : 0.01f * f1.y;
            *reinterpret_cast<float4*>(&H2s[(obase + u) * 128 + pb]) = hv;
        }
    }
    __syncthreads();   // H2 + staged w3 visible

    // ---- layer 3 (channels 3..28 only; 0..2 are masked) + fire update ----
    {
        // grp4 0..3 handle {7,7,6,6} channels starting at {3,10,17,23}
        const int obase = (grp4 < 2) ? (3 + grp4 * 7) : (17 + (grp4 - 2) * 6);
        const int cnt   = (grp4 < 2) ? 7 : 6;
        float dxv[7];
#pragma unroll
        for (int u = 0; u < 7; ++u) dxv[u] = 0.f;
#pragma unroll 2
        for (int k = 0; k < 128; ++k) {
            float h = H2s[k * 128 + pix];
#pragma unroll
            for (int u = 0; u < 7; ++u)
                dxv[u] = fmaf(Ws[(obase + u) * 128 + k], h, dxv[u]);
        }
        // fire mask: uniform(fold_in(key, step), (B,H,W,1)) < 0.5  <=>  top bit 0
        uint32_t n = (uint32_t)(b * 4096 + gy * 64 + gx);
        const uint32_t HALF = 32768u;
        uint32_t lo = (n < HALF) ? n : (n - HALF);
        uint32_t o0, o1;
        threefry2x32(fk0, fk1, lo, lo + HALF, o0, o1);
        uint32_t bits = (n < HALF) ? o0 : o1;
        bool fire = (bits & 0x80000000u) == 0u;

        int base = (b * kNCH) * kPix + gy * 64 + gx;
#pragma unroll
        for (int u = 0; u < 7; ++u) {
            if (u < cnt) {
                int idx = base + (obase + u) * kPix;
                float s = __ldg(&src[idx]);
                dst[idx] = fire ? (s + dxv[u]) : s;
            }
        }
    }
}

// ---------------------------------------------------------------------------
// reduce: mean over HW of channels 19..28, then softmax -> out (16, 10)
// ---------------------------------------------------------------------------
__global__ void __launch_bounds__(256) nca_reduce_kernel(float* __restrict__ out)
{
    int b = blockIdx.x;
    int tid = threadIdx.x;
    const float* st = g_state[0] + (b * kNCH + 19) * kPix;
    float acc[10];
#pragma unroll
    for (int c = 0; c < 10; ++c) acc[c] = 0.f;
    for (int i = tid; i < kPix; i += 256) {
#pragma unroll
        for (int c = 0; c < 10; ++c) acc[c] += st[c * kPix + i];
    }
#pragma unroll
    for (int c = 0; c < 10; ++c) {
#pragma unroll
        for (int off = 16; off > 0; off >>= 1)
            acc[c] += __shfl_xor_sync(0xffffffffu, acc[c], off);
    }
    __shared__ float sred[10][8];
    int wid = tid >> 5, lane = tid & 31;
    if (lane == 0) {
#pragma unroll
        for (int c = 0; c < 10; ++c) sred[c][wid] = acc[c];
    }
    __syncthreads();
    if (tid == 0) {
        float m[10];
        float mx = -1e30f;
#pragma unroll
        for (int c = 0; c < 10; ++c) {
            float s = 0.f;
#pragma unroll
            for (int w = 0; w < 8; ++w) s += sred[c][w];
            m[c] = s * (1.0f / 4096.0f);
            mx = fmaxf(mx, m[c]);
        }
        float den = 0.f;
        float e[10];
#pragma unroll
        for (int c = 0; c < 10; ++c) { e[c] = expf(m[c] - mx); den += e[c]; }
#pragma unroll
        for (int c = 0; c < 10; ++c) out[b * 10 + c] = e[c] / den;
    }
}

// ---------------------------------------------------------------------------
extern "C" void kernel_launch(void* const* d_in, const int* in_sizes, int n_in,
                              void* d_out, int out_size)
{
    (void)in_sizes; (void)n_in; (void)out_size;
    const float* x  = (const float*)d_in[0];
    const float* w1 = (const float*)d_in[1];
    const float* b1 = (const float*)d_in[2];
    const float* w2 = (const float*)d_in[3];
    const float* w3 = (const float*)d_in[4];
    float* out = (float*)d_out;

    cudaFuncSetAttribute(nca_step_kernel,
                         cudaFuncAttributeMaxDynamicSharedMemorySize, kSmemBytes);

    // hid-init key: fold_in(key(42), 10000)
    uint32_t hk0, hk1;
    threefry2x32(0u, 42u, 0u, 10000u, hk0, hk1);
    nca_init_kernel<<<(kStateElems + 255) / 256, 256>>>(x, hk0, hk1);

    for (int s = 0; s < kSteps; ++s) {
        uint32_t fk0, fk1;
        threefry2x32(0u, 42u, 0u, (uint32_t)s, fk0, fk1);
        nca_step_kernel<<<dim3(4, 8, 16), 512, kSmemBytes>>>(
            w1, b1, w2, w3, (float)s / 100.0f, fk0, fk1, s & 1);
    }
    nca_reduce_kernel<<<16, 256>>>(out);
}

// round 9
// speedup vs baseline: 1.2337x; 1.1259x over previous
#include <cuda_runtime.h>
#include <cstdint>

// ---------------------------------------------------------------------------
// ClassificationNCA: 20-step neural cellular automaton, fused per-step kernel.
// Round 7: exact round-4 shape + inner loops (best so far, 284us/step), with
// double-buffered weight staging and register prefetch so no barrier exposes
// LDG latency. Accumulation chains bit-identical to rounds 3-6.
// ---------------------------------------------------------------------------

#define kNCH 29
#define kBatch 16
#define kPix 4096
#define kStateElems (kBatch * kNCH * kPix)
#define kSteps 20

// smem layout (floats)
#define kH1Off 16384              /* region A: P[88][128] / H2[128][128] */
#define kWsOff (kH1Off + 32768)   /* H1 = 256*128 */
#define kWsBuf 4096               /* two 16KB staging buffers */
#define kSmemFloats (kWsOff + 2 * kWsBuf)
#define kSmemBytes (kSmemFloats * 4)   /* 229376 B -> 1 CTA/SM */

__device__ float g_state[2][kStateElems];

// ---------------------------------------------------------------------------
// packed f32x2 helpers
// ---------------------------------------------------------------------------
__device__ __forceinline__ unsigned long long pack2(float x, float y)
{
    unsigned long long r;
    asm("mov.b64 %0, {%1, %2};" : "=l"(r) : "f"(x), "f"(y));
    return r;
}
__device__ __forceinline__ unsigned long long ffma2(unsigned long long a,
                                                    unsigned long long b,
                                                    unsigned long long c)
{
    unsigned long long d;
    asm("fma.rn.f32x2 %0, %1, %2, %3;" : "=l"(d) : "l"(a), "l"(b), "l"(c));
    return d;
}
__device__ __forceinline__ float2 unpack2(unsigned long long v)
{
    float2 f;
    asm("mov.b64 {%0, %1}, %2;" : "=f"(f.x), "=f"(f.y) : "l"(v));
    return f;
}

// ---------------------------------------------------------------------------
// threefry2x32, JAX key schedule (20 rounds)
// ---------------------------------------------------------------------------
#define TF_ROUND(r) { x0 += x1; x1 = (x1 << (r)) | (x1 >> (32 - (r))); x1 ^= x0; }
__host__ __device__ inline void threefry2x32(uint32_t k0, uint32_t k1,
                                             uint32_t x0, uint32_t x1,
                                             uint32_t &o0, uint32_t &o1)
{
    uint32_t k2 = k0 ^ k1 ^ 0x1BD11BDAu;
    x0 += k0; x1 += k1;
    TF_ROUND(13) TF_ROUND(15) TF_ROUND(26) TF_ROUND(6)
    x0 += k1; x1 += k2 + 1u;
    TF_ROUND(17) TF_ROUND(29) TF_ROUND(16) TF_ROUND(24)
    x0 += k2; x1 += k0 + 2u;
    TF_ROUND(13) TF_ROUND(15) TF_ROUND(26) TF_ROUND(6)
    x0 += k0; x1 += k1 + 3u;
    TF_ROUND(17) TF_ROUND(29) TF_ROUND(16) TF_ROUND(24)
    x0 += k1; x1 += k2 + 4u;
    TF_ROUND(13) TF_ROUND(15) TF_ROUND(26) TF_ROUND(6)
    x0 += k2; x1 += k0 + 5u;
    o0 = x0; o1 = x1;
}

// XLA ErfInv (f32), Giles polynomial — matches jax.lax.erf_inv
__device__ inline float erfinv_f(float x)
{
    float w = -log1pf(-x * x);
    float p;
    if (w < 5.0f) {
        w -= 2.5f;
        p = 2.81022636e-08f;
        p = fmaf(p, w, 3.43273939e-07f);
        p = fmaf(p, w, -3.5233877e-06f);
        p = fmaf(p, w, -4.39150654e-06f);
        p = fmaf(p, w, 0.00021858087f);
        p = fmaf(p, w, -0.00125372503f);
        p = fmaf(p, w, -0.00417768164f);
        p = fmaf(p, w, 0.246640727f);
        p = fmaf(p, w, 1.50140941f);
    } else {
        w = sqrtf(w) - 3.0f;
        p = -0.000200214257f;
        p = fmaf(p, w, 0.000100950558f);
        p = fmaf(p, w, 0.00134934322f);
        p = fmaf(p, w, -0.00367342844f);
        p = fmaf(p, w, 0.00573950773f);
        p = fmaf(p, w, -0.0076224613f);
        p = fmaf(p, w, 0.00943887047f);
        p = fmaf(p, w, 1.00167406f);
        p = fmaf(p, w, 2.83297682f);
    }
    return p * x;
}

// ---------------------------------------------------------------------------
// init: channels 0-2 = image (both buffers), 3-18 = threefry normal, 19-28 = 0
// ---------------------------------------------------------------------------
__global__ void __launch_bounds__(256) nca_init_kernel(const float* __restrict__ x,
                                                       uint32_t hk0, uint32_t hk1)
{
    int e = blockIdx.x * 256 + threadIdx.x;
    if (e >= kStateElems) return;
    int b = e / (kNCH * kPix);
    int r = e - b * (kNCH * kPix);
    int c = r / kPix;
    int pix = r - c * kPix;

    if (c < 3) {
        float v = x[(b * 3 + c) * kPix + pix];
        g_state[0][e] = v;
        g_state[1][e] = v;
    } else if (c < 19) {
        const uint32_t HALF = 524288u;  // (16*16*4096)/2
        uint32_t i = (uint32_t)((b * 16 + (c - 3)) * kPix + pix);
        uint32_t lo = (i < HALF) ? i : (i - HALF);
        uint32_t o0, o1;
        threefry2x32(hk0, hk1, lo, lo + HALF, o0, o1);
        uint32_t bits = (i < HALF) ? o0 : o1;
        float f = __uint_as_float((bits >> 9) | 0x3f800000u) - 1.0f;
        const float LOV = -0.99999994f;               // nextafter(-1, 0)
        float u = fmaxf(LOV, f * 2.0f + LOV);         // (hi - lo) rounds to 2.0f
        float z = 1.41421356f * erfinv_f(u);
        g_state[0][e] = 0.5f + 0.225f * z;
    } else {
        g_state[0][e] = 0.0f;
    }
}

// ---------------------------------------------------------------------------
// weight stage stream (transposed, NOT duplicated — round-4 layout):
//  g in [0,8):   layer1, chunk c=g>>2, kstage s=g&3, ks=s*22  (22 k x 128 outs)
//  g in [8,16):  layer2, kstage s=g-8, ks=s*32                (32 k x 128 outs)
//  g == 16:      w3 verbatim (3712 floats) into Ws buf0
//  buffer for stage g: Ws + (g&1)*kWsBuf
//  invariant: entering stage-g compute, pf holds stage g+1's weights.
// ---------------------------------------------------------------------------
__device__ __forceinline__ void stage_prefetch(int g, int tid,
    const float* __restrict__ w1, const float* __restrict__ w2,
    const float* __restrict__ w3, float pf[8])
{
    if (g < 8) {
        int c = g >> 2, s = g & 3, ks = s * 22;
#pragma unroll
        for (int t = 0; t < 6; ++t) {
            int i = tid + t * 512;
            if (i < 22 * 128) {
                int kk = i >> 7, ol = i & 127;
                int row = ((ol >> 3) << 4) + c * 8 + (ol & 7);
                pf[t] = __ldg(&w1[row * 88 + ks + kk]);
            }
        }
    } else if (g < 16) {
        int s = g - 8, ks = s * 32;
#pragma unroll
        for (int t = 0; t < 8; ++t) {
            int i = tid + t * 512;
            int kk = i >> 7, ol = i & 127;
            pf[t] = __ldg(&w2[ol * 256 + ks + kk]);
        }
    } else if (g == 16) {
#pragma unroll
        for (int t = 0; t < 8; ++t) {
            int i = tid + t * 512;
            if (i < 3712) pf[t] = __ldg(&w3[i]);
        }
    }
}

__device__ __forceinline__ void stage_store(int g, int tid, float* Ws, float pf[8])
{
    if (g < 8) {
        float* buf = Ws + (g & 1) * kWsBuf;
#pragma unroll
        for (int t = 0; t < 6; ++t) {
            int i = tid + t * 512;
            if (i < 22 * 128) buf[i] = pf[t];
        }
    } else if (g < 16) {
        float* buf = Ws + (g & 1) * kWsBuf;
#pragma unroll
        for (int t = 0; t < 8; ++t) buf[tid + t * 512] = pf[t];
    } else if (g == 16) {
        // buf index (16&1)==0 -> Ws[0:3712) holds w3 verbatim
#pragma unroll
        for (int t = 0; t < 8; ++t) {
            int i = tid + t * 512;
            if (i < 3712) Ws[i] = pf[t];
        }
    }
}

// ---------------------------------------------------------------------------
// fused NCA step: perception -> 88->256->128->29 MLP -> fire-masked update
// block = 128 pixels (16x8 tile), 512 threads, grid (4, 8, 16), 1 CTA/SM
// ---------------------------------------------------------------------------
__global__ void __launch_bounds__(512, 1) nca_step_kernel(
    const float* __restrict__ w1, const float* __restrict__ b1,
    const float* __restrict__ w2, const float* __restrict__ w3,
    float tval, uint32_t fk0, uint32_t fk1, int srcbuf)
{
    extern __shared__ float smem[];
    float* P   = smem;           // [88][128]
    float* H1s = smem + kH1Off;  // [256][128]
    float* H2s = smem;           // [128][128] (reuses P region)
    float* Ws  = smem + kWsOff;  // 2 x 4096-float staging buffers

    const float* __restrict__ src = g_state[srcbuf];
    float* __restrict__ dst = g_state[srcbuf ^ 1];

    const int tid = threadIdx.x;
    const int b  = blockIdx.z;
    const int x0 = blockIdx.x * 16;
    const int y0 = blockIdx.y * 8;
    const int pix  = tid & 127;
    const int grp4 = tid >> 7;          // 0..3
    const int tx = pix & 15;
    const int ty = pix >> 4;
    const int gx = x0 + tx;
    const int gy = y0 + ty;

    float pf[8];
    // prefetch stage 0; its latency overlaps perception's global loads
    stage_prefetch(0, tid, w1, w2, w3, pf);

    // ---- phase 1: perception (s, sobel_x, sobel_y, t) -> P ----
    {
        const float* sb = src + b * (kNCH * kPix);
        const int cbeg = grp4 * 8;
        const int cend = (cbeg + 8 < 29) ? cbeg + 8 : 29;
        const bool ym = gy > 0, yp = gy < 63, xm = gx > 0, xp = gx < 63;
        for (int c = cbeg; c < cend; ++c) {
            const float* sc = sb + c * kPix;
            float v11 = __ldg(&sc[gy * 64 + gx]);
            float v01 = ym ? __ldg(&sc[(gy - 1) * 64 + gx]) : 0.f;
            float v21 = yp ? __ldg(&sc[(gy + 1) * 64 + gx]) : 0.f;
            float v10 = xm ? __ldg(&sc[gy * 64 + gx - 1]) : 0.f;
            float v12 = xp ? __ldg(&sc[gy * 64 + gx + 1]) : 0.f;
            float v00 = (ym && xm) ? __ldg(&sc[(gy - 1) * 64 + gx - 1]) : 0.f;
            float v02 = (ym && xp) ? __ldg(&sc[(gy - 1) * 64 + gx + 1]) : 0.f;
            float v20 = (yp && xm) ? __ldg(&sc[(gy + 1) * 64 + gx - 1]) : 0.f;
            float v22 = (yp && xp) ? __ldg(&sc[(gy + 1) * 64 + gx + 1]) : 0.f;
            float sx = ((v02 - v00) + 2.0f * (v12 - v10) + (v22 - v20)) * 0.125f;
            float sy = ((v20 - v00) + 2.0f * (v21 - v01) + (v22 - v02)) * 0.125f;
            P[c * 128 + pix] = v11;
            P[(29 + c) * 128 + pix] = sx;
            P[(58 + c) * 128 + pix] = sy;
        }
        if (grp4 == 0) P[87 * 128 + pix] = tval;
    }

    stage_store(0, tid, Ws, pf);
    stage_prefetch(1, tid, w1, w2, w3, pf);
    __syncthreads();   // P ready, Ws buf0 ready

    const int og = tid >> 5;          // warp id 0..15 (uniform -> broadcast LDS)
    const int pb = (tid & 31) << 2;   // pixel base, 4 pixels / thread

    // ---- layer 1: h1 = leaky(W1 @ p + b1), 256 outs, k = 88 (2 chunks x 4x22) ----
    for (int c = 0; c < 2; ++c) {
        const int obase = og * 16 + c * 8;
        unsigned long long acc[4][4];
#pragma unroll
        for (int p = 0; p < 4; ++p) {
            unsigned long long bp = pack2(__ldg(&b1[obase + 2 * p]),
                                          __ldg(&b1[obase + 2 * p + 1]));
            acc[p][0] = bp; acc[p][1] = bp; acc[p][2] = bp; acc[p][3] = bp;
        }
        for (int s = 0; s < 4; ++s) {
            const int g = c * 4 + s;
            const float* buf = Ws + (g & 1) * kWsBuf;
            const int ks = s * 22;
#pragma unroll 2
            for (int kk = 0; kk < 22; ++kk) {
                float4 pv = *reinterpret_cast<const float4*>(&P[(ks + kk) * 128 + pb]);
                const ulonglong2 wA = *reinterpret_cast<const ulonglong2*>(&buf[kk * 128 + og * 8]);
                const ulonglong2 wB = *reinterpret_cast<const ulonglong2*>(&buf[kk * 128 + og * 8 + 4]);
                unsigned long long px[4];
                px[0] = pack2(pv.x, pv.x); px[1] = pack2(pv.y, pv.y);
                px[2] = pack2(pv.z, pv.z); px[3] = pack2(pv.w, pv.w);
#pragma unroll
                for (int j = 0; j < 4; ++j) {
                    acc[0][j] = ffma2(wA.x, px[j], acc[0][j]);
                    acc[1][j] = ffma2(wA.y, px[j], acc[1][j]);
                    acc[2][j] = ffma2(wB.x, px[j], acc[2][j]);
                    acc[3][j] = ffma2(wB.y, px[j], acc[3][j]);
                }
            }
            stage_store(g + 1, tid, Ws, pf);
            stage_prefetch(g + 2, tid, w1, w2, w3, pf);
            __syncthreads();
        }
#pragma unroll
        for (int p = 0; p < 4; ++p) {
            float lo[4], hi[4];
#pragma unroll
            for (int j = 0; j < 4; ++j) {
                float2 f = unpack2(acc[p][j]);
                lo[j] = f.x >= 0.f ? f.x : 0.01f * f.x;
                hi[j] = f.y >= 0.f ? f.y : 0.01f * f.y;
            }
            *reinterpret_cast<float4*>(&H1s[(obase + 2 * p) * 128 + pb]) =
                make_float4(lo[0], lo[1], lo[2], lo[3]);
            *reinterpret_cast<float4*>(&H1s[(obase + 2 * p + 1) * 128 + pb]) =
                make_float4(hi[0], hi[1], hi[2], hi[3]);
        }
    }
    __syncthreads();   // all H1 visible before layer2 reads it

    // ---- layer 2: h2 = leaky(W2 @ h1), 128 outs, k = 256 (8 x 32) ----
    {
        const int obase = og * 8;
        unsigned long long acc[4][4];
#pragma unroll
        for (int p = 0; p < 4; ++p) {
            acc[p][0] = 0ull; acc[p][1] = 0ull; acc[p][2] = 0ull; acc[p][3] = 0ull;
        }
        for (int s = 0; s < 8; ++s) {
            const int g = 8 + s;
            const float* buf = Ws + (g & 1) * kWsBuf;
            const int ks = s * 32;
#pragma unroll 2
            for (int kk = 0; kk < 32; ++kk) {
                float4 hv = *reinterpret_cast<const float4*>(&H1s[(ks + kk) * 128 + pb]);
                const ulonglong2 wA = *reinterpret_cast<const ulonglong2*>(&buf[kk * 128 + og * 8]);
                const ulonglong2 wB = *reinterpret_cast<const ulonglong2*>(&buf[kk * 128 + og * 8 + 4]);
                unsigned long long px[4];
                px[0] = pack2(hv.x, hv.x); px[1] = pack2(hv.y, hv.y);
                px[2] = pack2(hv.z, hv.z); px[3] = pack2(hv.w, hv.w);
#pragma unroll
                for (int j = 0; j < 4; ++j) {
                    acc[0][j] = ffma2(wA.x, px[j], acc[0][j]);
                    acc[1][j] = ffma2(wA.y, px[j], acc[1][j]);
                    acc[2][j] = ffma2(wB.x, px[j], acc[2][j]);
                    acc[3][j] = ffma2(wB.y, px[j], acc[3][j]);
                }
            }
            stage_store(g + 1, tid, Ws, pf);   // g=15 stores w3 into Ws buf0
            stage_prefetch(g + 2, tid, w1, w2, w3, pf);
            __syncthreads();
        }
#pragma unroll
        for (int p = 0; p < 4; ++p) {
            float lo[4], hi[4];
#pragma unroll
            for (int j = 0; j < 4; ++j) {
                float2 f = unpack2(acc[p][j]);
                lo[j] = f.x >= 0.f ? f.x : 0.01f * f.x;
                hi[j] = f.y >= 0.f ? f.y : 0.01f * f.y;
            }
            *reinterpret_cast<float4*>(&H2s[(obase + 2 * p) * 128 + pb]) =
                make_float4(lo[0], lo[1], lo[2], lo[3]);
            *reinterpret_cast<float4*>(&H2s[(obase + 2 * p + 1) * 128 + pb]) =
                make_float4(hi[0], hi[1], hi[2], hi[3]);
        }
    }
    __syncthreads();   // H2 + staged w3 visible

    // ---- layer 3 (channels 3..28 only; 0..2 are masked) + fire update ----
    {
        // grp4 0..3 handle {7,7,6,6} channels starting at {3,10,17,23}
        const int obase = (grp4 < 2) ? (3 + grp4 * 7) : (17 + (grp4 - 2) * 6);
        const int cnt   = (grp4 < 2) ? 7 : 6;
        float dxv[7];
#pragma unroll
        for (int u = 0; u < 7; ++u) dxv[u] = 0.f;
#pragma unroll 2
        for (int k = 0; k < 128; ++k) {
            float h = H2s[k * 128 + pix];
#pragma unroll
            for (int u = 0; u < 7; ++u)
                dxv[u] = fmaf(Ws[(obase + u) * 128 + k], h, dxv[u]);
        }
        // fire mask: uniform(fold_in(key, step), (B,H,W,1)) < 0.5  <=>  top bit 0
        uint32_t n = (uint32_t)(b * 4096 + gy * 64 + gx);
        const uint32_t HALF = 32768u;
        uint32_t lo = (n < HALF) ? n : (n - HALF);
        uint32_t o0, o1;
        threefry2x32(fk0, fk1, lo, lo + HALF, o0, o1);
        uint32_t bits = (n < HALF) ? o0 : o1;
        bool fire = (bits & 0x80000000u) == 0u;

        int base = (b * kNCH) * kPix + gy * 64 + gx;
#pragma unroll
        for (int u = 0; u < 7; ++u) {
            if (u < cnt) {
                int idx = base + (obase + u) * kPix;
                float s = __ldg(&src[idx]);
                dst[idx] = fire ? (s + dxv[u]) : s;
            }
        }
    }
}

// ---------------------------------------------------------------------------
// reduce: mean over HW of channels 19..28, then softmax -> out (16, 10)
// ---------------------------------------------------------------------------
__global__ void __launch_bounds__(256) nca_reduce_kernel(float* __restrict__ out)
{
    int b = blockIdx.x;
    int tid = threadIdx.x;
    const float* st = g_state[0] + (b * kNCH + 19) * kPix;
    float acc[10];
#pragma unroll
    for (int c = 0; c < 10; ++c) acc[c] = 0.f;
    for (int i = tid; i < kPix; i += 256) {
#pragma unroll
        for (int c = 0; c < 10; ++c) acc[c] += st[c * kPix + i];
    }
#pragma unroll
    for (int c = 0; c < 10; ++c) {
#pragma unroll
        for (int off = 16; off > 0; off >>= 1)
            acc[c] += __shfl_xor_sync(0xffffffffu, acc[c], off);
    }
    __shared__ float sred[10][8];
    int wid = tid >> 5, lane = tid & 31;
    if (lane == 0) {
#pragma unroll
        for (int c = 0; c < 10; ++c) sred[c][wid] = acc[c];
    }
    __syncthreads();
    if (tid == 0) {
        float m[10];
        float mx = -1e30f;
#pragma unroll
        for (int c = 0; c < 10; ++c) {
            float s = 0.f;
#pragma unroll
            for (int w = 0; w < 8; ++w) s += sred[c][w];
            m[c] = s * (1.0f / 4096.0f);
            mx = fmaxf(mx, m[c]);
        }
        float den = 0.f;
        float e[10];
#pragma unroll
        for (int c = 0; c < 10; ++c) { e[c] = expf(m[c] - mx); den += e[c]; }
#pragma unroll
        for (int c = 0; c < 10; ++c) out[b * 10 + c] = e[c] / den;
    }
}

// ---------------------------------------------------------------------------
extern "C" void kernel_launch(void* const* d_in, const int* in_sizes, int n_in,
                              void* d_out, int out_size)
{
    (void)in_sizes; (void)n_in; (void)out_size;
    const float* x  = (const float*)d_in[0];
    const float* w1 = (const float*)d_in[1];
    const float* b1 = (const float*)d_in[2];
    const float* w2 = (const float*)d_in[3];
    const float* w3 = (const float*)d_in[4];
    float* out = (float*)d_out;

    cudaFuncSetAttribute(nca_step_kernel,
                         cudaFuncAttributeMaxDynamicSharedMemorySize, kSmemBytes);

    // hid-init key: fold_in(key(42), 10000)
    uint32_t hk0, hk1;
    threefry2x32(0u, 42u, 0u, 10000u, hk0, hk1);
    nca_init_kernel<<<(kStateElems + 255) / 256, 256>>>(x, hk0, hk1);

    for (int s = 0; s < kSteps; ++s) {
        uint32_t fk0, fk1;
        threefry2x32(0u, 42u, 0u, (uint32_t)s, fk0, fk1);
        nca_step_kernel<<<dim3(4, 8, 16), 512, kSmemBytes>>>(
            w1, b1, w2, w3, (float)s / 100.0f, fk0, fk1, s & 1);
    }
    nca_reduce_kernel<<<16, 256>>>(out);
}